// round 1
// baseline (speedup 1.0000x reference)
#include <cuda_runtime.h>
#include <math.h>

#define NSPEC   7
#define NBATCH  64
#define NATOM   32
#define NAT_TOT 2048          // NBATCH*NATOM
#define DAEV    1008          // 7*16 + 28*32
#define TM      8             // atoms per MLP block

__device__ float g_aev[NAT_TOT * DAEV];
__device__ int   g_bucket[NSPEC * NAT_TOT];
__device__ int   g_cnt[NSPEC];

__device__ __forceinline__ float celu01(float x) {
    return x > 0.f ? x : 0.1f * (__expf(x * 10.f) - 1.f);
}

__global__ void k_init(float* out) {
    int t = threadIdx.x;
    if (t < NBATCH) out[t] = 0.f;
    if (t < NSPEC)  g_cnt[t] = 0;
}

__global__ void k_bucket(const int* __restrict__ species,
                         const float* __restrict__ sae,
                         float* __restrict__ out) {
    int a = blockIdx.x * blockDim.x + threadIdx.x;
    if (a >= NAT_TOT) return;
    int s = species[a];
    int idx = atomicAdd(&g_cnt[s], 1);
    g_bucket[s * NAT_TOT + idx] = a;
    atomicAdd(&out[a >> 5], sae[s]);
}

// One block per (batch, atom i): builds the 1008-wide AEV.
__global__ void __launch_bounds__(128)
k_aev(const int* __restrict__ species, const float* __restrict__ coords) {
    int bi = blockIdx.x;
    int b = bi >> 5, i = bi & 31;
    __shared__ float px[32], py[32], pz[32];
    __shared__ float dist[32], fcr[32], fca[32], ux[32], uy[32], uz[32];
    __shared__ int   sp[32];
    __shared__ float aev[DAEV];
    int t = threadIdx.x;

    if (t < 32) {
        px[t] = coords[(b * 32 + t) * 3 + 0];
        py[t] = coords[(b * 32 + t) * 3 + 1];
        pz[t] = coords[(b * 32 + t) * 3 + 2];
        sp[t] = species[b * 32 + t];
    }
    __syncthreads();

    if (t < 32) {
        float dx = px[t] - px[i], dy = py[t] - py[i], dz = pz[t] - pz[i];
        float d = sqrtf(dx * dx + dy * dy + dz * dz + 1e-12f);
        dist[t] = d;
        float inv = 1.f / d;
        ux[t] = dx * inv; uy[t] = dy * inv; uz[t] = dz * inv;
        const float PI = 3.14159265358979f;
        fcr[t] = (t != i && d < 5.1f) ? 0.5f * __cosf(PI * d / 5.1f) + 0.5f : 0.f;
        fca[t] = (t != i && d < 3.5f) ? 0.5f * __cosf(PI * d / 3.5f) + 0.5f : 0.f;
    }
    for (int k = t; k < DAEV; k += 128) aev[k] = 0.f;
    __syncthreads();

    // ---- radial: 32 neighbors x 16 shifts ----
    for (int k = t; k < 512; k += 128) {
        int j = k >> 4, r = k & 15;
        float fr = fcr[j];
        if (fr > 0.f) {
            float x = dist[j] - (0.8f + 0.26875f * (float)r);
            atomicAdd(&aev[sp[j] * 16 + r], 0.25f * __expf(-19.7f * x * x) * fr);
        }
    }

    // ---- angular: unordered pairs j<k (x2 for symmetry) ----
    for (int p = t; p < 496; p += 128) {
        int kk = (int)((1.f + sqrtf(1.f + 8.f * (float)p)) * 0.5f);
        while (kk * (kk - 1) / 2 > p) kk--;
        while ((kk + 1) * kk / 2 <= p) kk++;
        int j = p - kk * (kk - 1) / 2;

        float w = fca[j] * fca[kk];
        if (w > 0.f) {
            w *= 2.f;  // ordered-pair double count
            float cv = ux[j] * ux[kk] + uy[j] * uy[kk] + uz[j] * uz[kk];
            cv = 0.95f * fminf(1.f, fmaxf(-1.f, cv));
            float theta = acosf(cv);
            float avg = 0.5f * (dist[j] + dist[kk]);

            float f2[8];
            #pragma unroll
            for (int a2 = 0; a2 < 8; a2++) {
                float x = avg - (0.8f + 0.3375f * (float)a2);
                f2[a2] = __expf(-12.5f * x * x) * w;
            }
            int pa = min(sp[j], sp[kk]), pb = max(sp[j], sp[kk]);
            int base = 112 + (pa * 7 - (pa * (pa - 1)) / 2 + (pb - pa)) * 32;
            const float PI4 = 0.78539816339745f;
            #pragma unroll
            for (int z = 0; z < 4; z++) {
                float c = (1.f + __cosf(theta - ((float)z + 0.5f) * PI4)) * 0.5f;
                float f1 = (c > 1e-30f) ? __expf(14.1f * __logf(c)) : 0.f;
                #pragma unroll
                for (int a2 = 0; a2 < 8; a2++)
                    atomicAdd(&aev[base + z * 8 + a2], f1 * f2[a2]);
            }
        }
    }
    __syncthreads();

    for (int k = t; k < DAEV; k += 128) g_aev[bi * DAEV + k] = aev[k];
}

// One block per (ensemble*species, tile of TM same-species atoms).
__global__ void __launch_bounds__(256)
k_mlp(const float* __restrict__ W0, const float* __restrict__ b0,
      const float* __restrict__ W1, const float* __restrict__ b1,
      const float* __restrict__ W2, const float* __restrict__ b2,
      const float* __restrict__ W3, const float* __restrict__ b3,
      float* __restrict__ out) {
    int es = blockIdx.x;               // e*7 + s
    int s = es % 7;
    int n = g_cnt[s];
    int m0 = blockIdx.y * TM;
    if (m0 >= n) return;

    __shared__ float sA[TM * DAEV];    // aev tile; later reused for h1/h2
    __shared__ float sH0[TM * 256];
    __shared__ int   atoms[TM];
    int t = threadIdx.x;

    if (t < TM) atoms[t] = (m0 + t < n) ? g_bucket[s * NAT_TOT + m0 + t] : -1;
    __syncthreads();

    for (int k = t; k < TM * DAEV; k += 256) {
        int m = k / DAEV, d = k - m * DAEV;
        int am = atoms[m];
        sA[k] = (am >= 0) ? g_aev[am * DAEV + d] : 0.f;
    }
    __syncthreads();

    // ---- layer 0: 1008 -> 256 ----
    {
        const float* W = W0 + (size_t)es * DAEV * 256;
        float acc[TM];
        #pragma unroll
        for (int m = 0; m < TM; m++) acc[m] = 0.f;
        for (int d = 0; d < DAEV; d += 4) {
            float w0 = W[(d + 0) * 256 + t];
            float w1 = W[(d + 1) * 256 + t];
            float w2 = W[(d + 2) * 256 + t];
            float w3 = W[(d + 3) * 256 + t];
            #pragma unroll
            for (int m = 0; m < TM; m++) {
                float4 a = *(const float4*)&sA[m * DAEV + d];
                acc[m] = fmaf(a.x, w0, acc[m]);
                acc[m] = fmaf(a.y, w1, acc[m]);
                acc[m] = fmaf(a.z, w2, acc[m]);
                acc[m] = fmaf(a.w, w3, acc[m]);
            }
        }
        float bb = b0[es * 256 + t];
        #pragma unroll
        for (int m = 0; m < TM; m++) sH0[m * 256 + t] = celu01(acc[m] + bb);
    }
    __syncthreads();

    // ---- layer 1: 256 -> 192 (h1 overwrites dead aev region) ----
    float* sH1 = sA;
    if (t < 192) {
        const float* W = W1 + (size_t)es * 256 * 192;
        float acc[TM];
        #pragma unroll
        for (int m = 0; m < TM; m++) acc[m] = 0.f;
        for (int d = 0; d < 256; d += 4) {
            float w0 = W[(d + 0) * 192 + t];
            float w1 = W[(d + 1) * 192 + t];
            float w2 = W[(d + 2) * 192 + t];
            float w3 = W[(d + 3) * 192 + t];
            #pragma unroll
            for (int m = 0; m < TM; m++) {
                float4 a = *(const float4*)&sH0[m * 256 + d];
                acc[m] = fmaf(a.x, w0, acc[m]);
                acc[m] = fmaf(a.y, w1, acc[m]);
                acc[m] = fmaf(a.z, w2, acc[m]);
                acc[m] = fmaf(a.w, w3, acc[m]);
            }
        }
        float bb = b1[es * 192 + t];
        #pragma unroll
        for (int m = 0; m < TM; m++) sH1[m * 192 + t] = celu01(acc[m] + bb);
    }
    __syncthreads();

    // ---- layer 2: 192 -> 160 ----
    float* sH2 = sA + TM * 192;
    if (t < 160) {
        const float* W = W2 + (size_t)es * 192 * 160;
        float acc[TM];
        #pragma unroll
        for (int m = 0; m < TM; m++) acc[m] = 0.f;
        for (int d = 0; d < 192; d += 4) {
            float w0 = W[(d + 0) * 160 + t];
            float w1 = W[(d + 1) * 160 + t];
            float w2 = W[(d + 2) * 160 + t];
            float w3 = W[(d + 3) * 160 + t];
            #pragma unroll
            for (int m = 0; m < TM; m++) {
                float4 a = *(const float4*)&sH1[m * 192 + d];
                acc[m] = fmaf(a.x, w0, acc[m]);
                acc[m] = fmaf(a.y, w1, acc[m]);
                acc[m] = fmaf(a.z, w2, acc[m]);
                acc[m] = fmaf(a.w, w3, acc[m]);
            }
        }
        float bb = b2[es * 160 + t];
        #pragma unroll
        for (int m = 0; m < TM; m++) sH2[m * 160 + t] = celu01(acc[m] + bb);
    }
    __syncthreads();

    // ---- layer 3: 160 -> 1, accumulate energy ----
    if (t < TM) {
        int am = atoms[t];
        if (am >= 0) {
            const float* W = W3 + (size_t)es * 160;
            float acc = b3[es];
            for (int f = 0; f < 160; f++) acc = fmaf(sH2[t * 160 + f], W[f], acc);
            atomicAdd(&out[am >> 5], acc * 0.125f);   // /8 ensemble avg
        }
    }
}

extern "C" void kernel_launch(void* const* d_in, const int* in_sizes, int n_in,
                              void* d_out, int out_size) {
    const int*   species = (const int*)d_in[0];
    const float* coords  = (const float*)d_in[1];
    const float* W0 = (const float*)d_in[2];
    const float* b0 = (const float*)d_in[3];
    const float* W1 = (const float*)d_in[4];
    const float* b1 = (const float*)d_in[5];
    const float* W2 = (const float*)d_in[6];
    const float* b2 = (const float*)d_in[7];
    const float* W3 = (const float*)d_in[8];
    const float* b3 = (const float*)d_in[9];
    const float* sae = (const float*)d_in[10];
    float* out = (float*)d_out;

    k_init<<<1, 64>>>(out);
    k_bucket<<<8, 256>>>(species, sae, out);
    k_aev<<<NAT_TOT, 128>>>(species, coords);
    k_mlp<<<dim3(56, (NAT_TOT + TM - 1) / TM), 256>>>(W0, b0, W1, b1, W2, b2, W3, b3, out);
}